// round 4
// baseline (speedup 1.0000x reference)
#include <cuda_runtime.h>
#include <stdint.h>

// UniformShardedEmbeddingBags: weights [E,T,D] fp32, indices [B,T,L] int32 -> out [B,T,D] fp32
// E=200000, T=16, D=64, B=4096, L=20
#define EB_E 200000
#define EB_T 16
#define EB_D 64
#define EB_L 20
#define EB_B 4096

// One WARP per bag. Each lane owns one float2 (8B) of the 256B row:
// 32 lanes x 8B = the same two coalesced 128B lines per gathered row, but each
// pending load now pins only 2 registers -> ~2x more loads in flight per warp
// under the 32-reg full-occupancy budget (SM-wide outstanding ~640 vs ~320).
//
// Indices: lanes 0..19 each load one index (single coalesced LDG per bag),
// then __shfl_sync broadcasts inside the unrolled loop — removes 19/20 of the
// scalar index LDGs from the LSU path.
//
// Grid stays TABLE-MAJOR (512 blocks per table, 8 bags per block) so the
// concurrent working set spans ~2-3 tables and L2 keeps capturing the ~1.22x
// per-table row reuse (we are at the DRAM byte floor already).
__global__ __launch_bounds__(256, 8) void embbag_kernel(
    const float* __restrict__ weights,
    const int* __restrict__ indices,
    float* __restrict__ out)
{
    const int warp = threadIdx.x >> 5;                  // 0..7
    const int lane = threadIdx.x & 31;

    const int t = blockIdx.x >> 9;                      // table 0..15 (512 blocks each)
    const int b = ((blockIdx.x & 511) << 3) + warp;     // batch 0..4095
    const int bag = b * EB_T + t;

    // Lanes 0..19 fetch this bag's indices; one coalesced transaction.
    int myidx = 0;
    if (lane < EB_L) myidx = __ldg(indices + (size_t)bag * EB_L + lane);

    const float2* wbase = reinterpret_cast<const float2*>(weights) + lane;

    float2 acc = make_float2(0.f, 0.f);

#pragma unroll
    for (int l = 0; l < EB_L; ++l) {
        int e = __shfl_sync(0xFFFFFFFFu, myidx, l);
        float2 v = __ldg(wbase + ((size_t)e * EB_T + t) * (EB_D / 2));
        acc.x += v.x; acc.y += v.y;
    }

    reinterpret_cast<float2*>(out)[(size_t)bag * 32 + lane] = acc;
}

extern "C" void kernel_launch(void* const* d_in, const int* in_sizes, int n_in,
                              void* d_out, int out_size)
{
    // weights = 204,800,000 elems ; indices = 1,310,720 elems
    const float* weights = (const float*)d_in[0];
    const int*   indices = (const int*)d_in[1];
    if (n_in >= 2 && in_sizes[0] < in_sizes[1]) {
        weights = (const float*)d_in[1];
        indices = (const int*)d_in[0];
    }
    float* out = (float*)d_out;

    const int block = 256;                 // 8 warps = 8 bags per block
    const int grid = EB_T * 512;           // 8192 blocks, table-major
    embbag_kernel<<<grid, block>>>(weights, indices, out);
}